// round 13
// baseline (speedup 1.0000x reference)
#include <cuda_runtime.h>
#include <cuda_bf16.h>
#include <cuda_fp16.h>
#include <cuda_fp8.h>
#include <cstdint>

#define NB 8192
#define DD 256
#define BM 128
#define BN 128
#define NT 64
#define NTILES (NT * (NT + 1) / 2)      // 2080 upper-triangular tiles

#define ROW_B 144                        // padded byte stride (128 data + 16 pad)
#define CHUNK_BYTES (BM * ROW_B)         // 18432 B per matrix per chunk
#define OFF_A0 0
#define OFF_B0 (OFF_A0 + CHUNK_BYTES)
#define OFF_A1 (OFF_B0 + CHUNK_BYTES)
#define OFF_B1 (OFF_A1 + CHUNK_BYTES)
#define OFF_LAB (OFF_B1 + CHUNK_BYTES)          // 256 * 4
#define OFF_RACC (OFF_LAB + 1024)               // 128 floats (denom row)
#define OFF_CACC (OFF_RACC + 512)               // 128 floats (denom col)
#define SMEM_BYTES (OFF_CACC + 512)             // 75776 B

// exact-f16 epilogue constants: l2shift = s*C2H + KH  (scale 2^14.000554...)
#define C2H  20.609375f                  // exact in f16
#define KH   -6.609375f                  // exact in f16
#define C2F  20.609929155603256f         // (1/T)*log2(e), f32-exact path for S1
#define LN2  0.6931471805599453f
#define SHIFT_LN 9.7044446f              // (KH + C2F) * ln2 = 14.000554155 * ln2
#define EX_THR 0.74403f                  // 2^(0.3*C2H + KH)  <=> s > 0.3
#define NEG_SLOPE 1.4285714285714286f
#define NEG_W 0.3f

// g_rowstats layout: [0]=D(denom,scaled) [1]=S1 [2]=W1 [3]=Pex(scaled) [4]=Thard(scaled)
__device__ uint8_t g_nrm[NB * DD];
__device__ float g_rowstats[5 * NB];

// ---------------------------------------------------------------- helpers
__device__ __forceinline__ void cp_async16(unsigned dst, const void* src) {
    asm volatile("cp.async.cg.shared.global [%0], [%1], 16;\n" :: "r"(dst), "l"(src));
}
__device__ __forceinline__ void ldsm4(uint32_t& r0, uint32_t& r1, uint32_t& r2, uint32_t& r3,
                                      unsigned addr) {
    asm volatile("ldmatrix.sync.aligned.m8n8.x4.shared.b16 {%0,%1,%2,%3}, [%4];\n"
                 : "=r"(r0), "=r"(r1), "=r"(r2), "=r"(r3) : "r"(addr));
}
__device__ __forceinline__ void mma16832h(uint32_t* d, const uint32_t* a, const uint32_t* b) {
    asm volatile(
        "mma.sync.aligned.m16n8k32.row.col.f16.e4m3.e4m3.f16 "
        "{%0,%1}, {%2,%3,%4,%5}, {%6,%7}, {%0,%1};\n"
        : "+r"(d[0]), "+r"(d[1])
        : "r"(a[0]), "r"(a[1]), "r"(a[2]), "r"(a[3]), "r"(b[0]), "r"(b[1]));
}
__device__ __forceinline__ uint32_t ex2_f16x2(uint32_t x) {
    uint32_t r;
    asm("ex2.approx.f16x2 %0, %1;" : "=r"(r) : "r"(x));
    return r;
}

__device__ __forceinline__ void load_chunk(const uint8_t* gA, const uint8_t* gB,
                                           unsigned sA, unsigned sB, int kc, int t) {
    const uint8_t* a = gA + kc * 128;
    const uint8_t* b = gB + kc * 128;
#pragma unroll
    for (int it = 0; it < 4; ++it) {
        int lin = t + it * 256;
        int r = lin >> 3, cc = lin & 7;
        unsigned dst = (unsigned)(r * ROW_B + cc * 16);
        cp_async16(sA + dst, a + (size_t)r * DD + cc * 16);
        cp_async16(sB + dst, b + (size_t)r * DD + cc * 16);
    }
    asm volatile("cp.async.commit_group;" ::: "memory");
}

// ------------------------------------------------- kernel 1: normalize -> e4m3, zero stats
__global__ void norm_zero_kernel(const float* __restrict__ feat) {
    int gt = blockIdx.x * 256 + threadIdx.x;
    if (gt < 5 * NB) g_rowstats[gt] = 0.0f;

    int warp = threadIdx.x >> 5;
    int lane = threadIdx.x & 31;
    int row = blockIdx.x * 8 + warp;

    const float4* src = reinterpret_cast<const float4*>(feat) + (size_t)row * (DD / 4) + lane * 2;
    float4 a = src[0];
    float4 b = src[1];
    float ss = a.x * a.x + a.y * a.y + a.z * a.z + a.w * a.w
             + b.x * b.x + b.y * b.y + b.z * b.z + b.w * b.w;
#pragma unroll
    for (int o = 16; o > 0; o >>= 1) ss += __shfl_xor_sync(0xffffffffu, ss, o);
    float inv = rsqrtf(ss);

    unsigned p0 = __nv_cvt_float2_to_fp8x2(make_float2(a.x * inv, a.y * inv),
                                           __NV_SATFINITE, __NV_E4M3);
    unsigned p1 = __nv_cvt_float2_to_fp8x2(make_float2(a.z * inv, a.w * inv),
                                           __NV_SATFINITE, __NV_E4M3);
    unsigned p2 = __nv_cvt_float2_to_fp8x2(make_float2(b.x * inv, b.y * inv),
                                           __NV_SATFINITE, __NV_E4M3);
    unsigned p3 = __nv_cvt_float2_to_fp8x2(make_float2(b.z * inv, b.w * inv),
                                           __NV_SATFINITE, __NV_E4M3);
    uint2 pk;
    pk.x = (p0 & 0xffffu) | (p1 << 16);
    pk.y = (p2 & 0xffffu) | (p3 << 16);
    reinterpret_cast<uint2*>(g_nrm)[(size_t)row * (DD / 8) + lane] = pk;
}

// ------------------------------------------------- kernel 2: fused FP8 GEMM + f16x2 epilogue
__global__ __launch_bounds__(256, 2)
void w2ml_main_kernel(const int* __restrict__ labels) {
    extern __shared__ __align__(1024) char smem[];
    const unsigned sbase = (unsigned)__cvta_generic_to_shared(smem);
    const int t = threadIdx.x;

    // decode linear tile id -> (bi, bj), bi <= bj
    int id = blockIdx.x;
    int bi = (int)((2.0f * NT + 1.0f -
                    sqrtf((2.0f * NT + 1.0f) * (2.0f * NT + 1.0f) - 8.0f * (float)id)) * 0.5f);
    while ((bi + 1) * (2 * NT - bi) / 2 <= id) ++bi;
    while (bi * (2 * NT - bi + 1) / 2 > id) --bi;
    const int bj = bi + (id - bi * (2 * NT - bi + 1) / 2);
    const bool diag = (bi == bj);
    const int i0 = bi * BM;
    const int j0 = bj * BN;

    int* sLab = reinterpret_cast<int*>(smem + OFF_LAB);
    float* rowAcc = reinterpret_cast<float*>(smem + OFF_RACC);   // [128] denom
    float* colAcc = reinterpret_cast<float*>(smem + OFF_CACC);   // [128] denom

    if (t < 128) sLab[t] = labels[i0 + t];
    else         sLab[t] = labels[j0 + t - 128];
    if (t < 128) { rowAcc[t] = 0.0f; colAcc[t] = 0.0f; }

    const int lane = t & 31;
    const int warpId = t >> 5;
    const int wm = warpId >> 2;
    const int wn = warpId & 3;

    const uint8_t* gA = g_nrm + (size_t)i0 * DD;
    const uint8_t* gB = g_nrm + (size_t)j0 * DD;

    load_chunk(gA, gB, sbase + OFF_A0, sbase + OFF_B0, 0, t);
    load_chunk(gA, gB, sbase + OFF_A1, sbase + OFF_B1, 1, t);

    const unsigned aRow = (unsigned)((wm * 64 + (lane & 15)) * ROW_B + (lane >> 4) * 16);
    const unsigned bRow = (unsigned)((wn * 32 + (lane & 7) + ((lane >> 4) << 3)) * ROW_B
                                     + ((lane >> 3) & 1) * 16);

    uint32_t acc[4][4][2];
#pragma unroll
    for (int mi = 0; mi < 4; ++mi)
#pragma unroll
        for (int ni = 0; ni < 4; ++ni) { acc[mi][ni][0] = 0u; acc[mi][ni][1] = 0u; }

    asm volatile("cp.async.wait_group 1;" ::: "memory");
    __syncthreads();

#pragma unroll
    for (int kb = 0; kb < 2; ++kb) {
        if (kb == 1) {
            asm volatile("cp.async.wait_group 0;" ::: "memory");
            __syncthreads();
        }
        const unsigned aBase = sbase + (kb ? OFF_A1 : OFF_A0) + aRow;
        const unsigned bBase = sbase + (kb ? OFF_B1 : OFF_B0) + bRow;
#pragma unroll
        for (int ks = 0; ks < 4; ++ks) {
            unsigned off = ks * 32;
            uint32_t bf[4][2];
#pragma unroll
            for (int np = 0; np < 2; ++np) {
                uint32_t r0, r1, r2, r3;
                ldsm4(r0, r1, r2, r3, bBase + np * (16 * ROW_B) + off);
                bf[np * 2][0] = r0;     bf[np * 2][1] = r1;
                bf[np * 2 + 1][0] = r2; bf[np * 2 + 1][1] = r3;
            }
#pragma unroll
            for (int mi = 0; mi < 4; ++mi) {
                uint32_t a[4];
                ldsm4(a[0], a[1], a[2], a[3], aBase + mi * (16 * ROW_B) + off);
#pragma unroll
                for (int ni = 0; ni < 4; ++ni) mma16832h(acc[mi][ni], a, bf[ni]);
            }
        }
    }

    // ---- epilogue: f16x2 SIMD hot path + rare-event branch ----
    const int qrow = lane >> 2;
    const int qc = (lane & 3) << 1;
    const __half2 c2h2 = __floats2half2_rn(C2H, C2H);
    const __half2 kh2 = __floats2half2_rn(KH, KH);

    int rl0[4], lbr[4][2];
#pragma unroll
    for (int mi = 0; mi < 4; ++mi) {
        rl0[mi] = wm * 64 + mi * 16 + qrow;
        lbr[mi][0] = sLab[rl0[mi]];
        lbr[mi][1] = sLab[rl0[mi] + 8];
    }

    float vrD[4][2];
#pragma unroll
    for (int mi = 0; mi < 4; ++mi) { vrD[mi][0] = 0.0f; vrD[mi][1] = 0.0f; }

#pragma unroll
    for (int ni = 0; ni < 4; ++ni) {
        const int c0 = wn * 32 + ni * 8 + qc;
        const int lj0 = sLab[128 + c0];
        const int lj1 = sLab[128 + c0 + 1];
        float vcD[2] = {0.0f, 0.0f};
#pragma unroll
        for (int mi = 0; mi < 4; ++mi) {
#pragma unroll
            for (int h = 0; h < 2; ++h) {
                const __half2 sh = *reinterpret_cast<const __half2*>(&acc[mi][ni][h]);
                const __half2 l2h = __hfma2(sh, c2h2, kh2);
                const uint32_t exu = ex2_f16x2(*reinterpret_cast<const uint32_t*>(&l2h));
                const float2 ef = __half22float2(*reinterpret_cast<const __half2*>(&exu));
                vrD[mi][h] += ef.x + ef.y;
                vcD[0] += ef.x;
                vcD[1] += ef.y;
                const int lb = lbr[mi][h];
                const bool rare0 = (lb == lj0) | (ef.x > EX_THR);
                const bool rare1 = (lb == lj1) | (ef.y > EX_THR);
                if (rare0 | rare1) {
                    const float2 sf = __half22float2(sh);
                    const int r = rl0[mi] + h * 8;
                    if (rare0) {
                        const int c = c0;
                        if (lb == lj0) {
                            if (diag && (r == c)) {           // self: exact cancel
                                vrD[mi][h] -= ef.x; vcD[0] -= ef.x;
                            } else {                          // true positive
                                const float l = fmaf(sf.x, C2F, -C2F) * LN2;
                                const float wp = (sf.x < 0.5f) ? (1.5f - sf.x) : 1.0f;
                                const float s1 = wp * l;
                                atomicAdd(&g_rowstats[NB + i0 + r], s1);
                                atomicAdd(&g_rowstats[2 * NB + i0 + r], wp);
                                atomicAdd(&g_rowstats[3 * NB + i0 + r], ef.x);
                                if (!diag) {
                                    atomicAdd(&g_rowstats[NB + j0 + c], s1);
                                    atomicAdd(&g_rowstats[2 * NB + j0 + c], wp);
                                    atomicAdd(&g_rowstats[3 * NB + j0 + c], ef.x);
                                }
                            }
                        } else {                              // hard negative
                            const float add = (sf.x - 0.3f) * ef.x;
                            atomicAdd(&g_rowstats[4 * NB + i0 + r], add);
                            if (!diag) atomicAdd(&g_rowstats[4 * NB + j0 + c], add);
                        }
                    }
                    if (rare1) {
                        const int c = c0 + 1;
                        if (lb == lj1) {
                            if (diag && (r == c)) {
                                vrD[mi][h] -= ef.y; vcD[1] -= ef.y;
                            } else {
                                const float l = fmaf(sf.y, C2F, -C2F) * LN2;
                                const float wp = (sf.y < 0.5f) ? (1.5f - sf.y) : 1.0f;
                                const float s1 = wp * l;
                                atomicAdd(&g_rowstats[NB + i0 + r], s1);
                                atomicAdd(&g_rowstats[2 * NB + i0 + r], wp);
                                atomicAdd(&g_rowstats[3 * NB + i0 + r], ef.y);
                                if (!diag) {
                                    atomicAdd(&g_rowstats[NB + j0 + c], s1);
                                    atomicAdd(&g_rowstats[2 * NB + j0 + c], wp);
                                    atomicAdd(&g_rowstats[3 * NB + j0 + c], ef.y);
                                }
                            }
                        } else {
                            const float add = (sf.y - 0.3f) * ef.y;
                            atomicAdd(&g_rowstats[4 * NB + i0 + r], add);
                            if (!diag) atomicAdd(&g_rowstats[4 * NB + j0 + c], add);
                        }
                    }
                }
            }
        }
        if (!diag) {
#pragma unroll
            for (int o = 0; o < 2; ++o) {
                vcD[o] += __shfl_xor_sync(0xffffffffu, vcD[o], 4);
                vcD[o] += __shfl_xor_sync(0xffffffffu, vcD[o], 8);
                vcD[o] += __shfl_xor_sync(0xffffffffu, vcD[o], 16);
            }
            if (lane < 4) {
                atomicAdd(&colAcc[c0], vcD[0]);
                atomicAdd(&colAcc[c0 + 1], vcD[1]);
            }
        }
    }

#pragma unroll
    for (int mi = 0; mi < 4; ++mi) {
#pragma unroll
        for (int h = 0; h < 2; ++h) {
            vrD[mi][h] += __shfl_xor_sync(0xffffffffu, vrD[mi][h], 1);
            vrD[mi][h] += __shfl_xor_sync(0xffffffffu, vrD[mi][h], 2);
            if ((lane & 3) == 0)
                atomicAdd(&rowAcc[rl0[mi] + h * 8], vrD[mi][h]);
        }
    }
    __syncthreads();

    if (t < 128) {
        atomicAdd(&g_rowstats[i0 + t], rowAcc[t]);
    } else if (!diag) {
        atomicAdd(&g_rowstats[j0 + (t - 128)], colAcc[t - 128]);
    }
}

// ------------------------------------------------- kernel 3: finalize to scalar
__global__ void finalize_kernel(const int* __restrict__ labels, float* __restrict__ out) {
    __shared__ int hist[1024];
    __shared__ float sp[256], sn[256];
    int t = threadIdx.x;
    for (int k = t; k < 1024; k += 256) hist[k] = 0;
    __syncthreads();
    for (int r = t; r < NB; r += 256) atomicAdd(&hist[labels[r]], 1);
    __syncthreads();

    float ps = 0.0f, ns = 0.0f;
    for (int r = t; r < NB; r += 256) {
        float denom = g_rowstats[r];             // scaled by 2^14.000554
        float S1 = g_rowstats[NB + r];
        float W1 = g_rowstats[2 * NB + r];
        float Pex = g_rowstats[3 * NB + r];      // same scale as denom
        float Th = g_rowstats[4 * NB + r];       // same scale
        float S2 = (denom - Pex) + NEG_SLOPE * Th;
        int pc_actual = hist[labels[r]] - 1;
        float pc = fmaxf((float)pc_actual, 1.0f);
        float nc = fmaxf((float)(NB - 1 - pc_actual), 1.0f);
        float logd = __logf(denom) - SHIFT_LN;   // remove exact 2^14.000554 scale
        ps -= (S1 - W1 * logd) / pc;
        ns += (S2 / denom) / nc;                 // scale cancels in ratio
    }
    sp[t] = ps; sn[t] = ns;
    __syncthreads();
#pragma unroll
    for (int s = 128; s > 0; s >>= 1) {
        if (t < s) { sp[t] += sp[t + s]; sn[t] += sn[t + s]; }
        __syncthreads();
    }
    if (t == 0) out[0] = sp[0] * (1.0f / NB) + NEG_W * (sn[0] * (1.0f / NB));
}

// ------------------------------------------------- launch
extern "C" void kernel_launch(void* const* d_in, const int* in_sizes, int n_in,
                              void* d_out, int out_size) {
    const float* feat;
    const int* labels;
    if (in_sizes[0] == NB * DD) {
        feat = (const float*)d_in[0];
        labels = (const int*)d_in[1];
    } else {
        feat = (const float*)d_in[1];
        labels = (const int*)d_in[0];
    }

    cudaFuncSetAttribute(w2ml_main_kernel,
                         cudaFuncAttributeMaxDynamicSharedMemorySize, SMEM_BYTES);

    norm_zero_kernel<<<NB / 8, 256>>>(feat);

    w2ml_main_kernel<<<NTILES, 256, SMEM_BYTES>>>(labels);

    finalize_kernel<<<1, 256>>>(labels, (float*)d_out);
}

// round 14
// speedup vs baseline: 1.0820x; 1.0820x over previous
#include <cuda_runtime.h>
#include <cuda_bf16.h>
#include <cuda_fp16.h>
#include <cuda_fp8.h>
#include <cstdint>

#define NB 8192
#define DD 256
#define BM 128
#define BN 128
#define NT 64
#define NTILES (NT * (NT + 1) / 2)      // 2080 upper-triangular tiles

#define ROW_B 144                        // padded byte stride (128 data + 16 pad)
#define CHUNK_BYTES (BM * ROW_B)         // 18432 B per matrix per chunk
#define OFF_A0 0
#define OFF_B0 (OFF_A0 + CHUNK_BYTES)
#define OFF_A1 (OFF_B0 + CHUNK_BYTES)
#define OFF_B1 (OFF_A1 + CHUNK_BYTES)
#define OFF_LAB (OFF_B1 + CHUNK_BYTES)          // 256 * 4
#define OFF_RACC (OFF_LAB + 1024)               // 128 floats (denom row)
#define OFF_CACC (OFF_RACC + 512)               // 128 floats (denom col)
#define SMEM_BYTES (OFF_CACC + 512)             // 75776 B  (x3 CTAs = 227328 <= 228KB)

#define C2 20.609929155603256f           // (1/T) * log2(e)
#define LN2 0.6931471805599453f
#define NEG_SLOPE 1.4285714285714286f    // (HARD_NEG_W-1)/(1-THR_NEG)
#define NEG_W 0.3f

// g_rowstats layout: [0]=D(denom)  [1]=S1  [2]=W1  [3]=Pex  [4]=Thard
__device__ uint8_t g_nrm[NB * DD];
__device__ float g_rowstats[5 * NB];

// ---------------------------------------------------------------- helpers
__device__ __forceinline__ void cp_async16(unsigned dst, const void* src) {
    asm volatile("cp.async.cg.shared.global [%0], [%1], 16;\n" :: "r"(dst), "l"(src));
}
__device__ __forceinline__ void ldsm4(uint32_t& r0, uint32_t& r1, uint32_t& r2, uint32_t& r3,
                                      unsigned addr) {
    asm volatile("ldmatrix.sync.aligned.m8n8.x4.shared.b16 {%0,%1,%2,%3}, [%4];\n"
                 : "=r"(r0), "=r"(r1), "=r"(r2), "=r"(r3) : "r"(addr));
}
// FP8 MMA with f16 accumulators (halves acc register file vs f32)
__device__ __forceinline__ void mma16832h(uint32_t* d, const uint32_t* a, const uint32_t* b) {
    asm volatile(
        "mma.sync.aligned.m16n8k32.row.col.f16.e4m3.e4m3.f16 "
        "{%0,%1}, {%2,%3,%4,%5}, {%6,%7}, {%0,%1};\n"
        : "+r"(d[0]), "+r"(d[1])
        : "r"(a[0]), "r"(a[1]), "r"(a[2]), "r"(a[3]), "r"(b[0]), "r"(b[1]));
}
__device__ __forceinline__ float ex2f(float x) {
    float r;
    asm("ex2.approx.ftz.f32 %0, %1;" : "=f"(r) : "f"(x));
    return r;
}

__device__ __forceinline__ void load_chunk(const uint8_t* gA, const uint8_t* gB,
                                           unsigned sA, unsigned sB, int kc, int t) {
    const uint8_t* a = gA + kc * 128;
    const uint8_t* b = gB + kc * 128;
#pragma unroll
    for (int it = 0; it < 4; ++it) {
        int lin = t + it * 256;
        int r = lin >> 3, cc = lin & 7;
        unsigned dst = (unsigned)(r * ROW_B + cc * 16);
        cp_async16(sA + dst, a + (size_t)r * DD + cc * 16);
        cp_async16(sB + dst, b + (size_t)r * DD + cc * 16);
    }
    asm volatile("cp.async.commit_group;" ::: "memory");
}

// ------------------------------------------------- kernel 1: normalize -> e4m3, zero stats
__global__ void norm_zero_kernel(const float* __restrict__ feat) {
    int gt = blockIdx.x * 256 + threadIdx.x;
    if (gt < 5 * NB) g_rowstats[gt] = 0.0f;

    int warp = threadIdx.x >> 5;
    int lane = threadIdx.x & 31;
    int row = blockIdx.x * 8 + warp;

    const float4* src = reinterpret_cast<const float4*>(feat) + (size_t)row * (DD / 4) + lane * 2;
    float4 a = src[0];
    float4 b = src[1];
    float ss = a.x * a.x + a.y * a.y + a.z * a.z + a.w * a.w
             + b.x * b.x + b.y * b.y + b.z * b.z + b.w * b.w;
#pragma unroll
    for (int o = 16; o > 0; o >>= 1) ss += __shfl_xor_sync(0xffffffffu, ss, o);
    float inv = rsqrtf(ss);

    unsigned p0 = __nv_cvt_float2_to_fp8x2(make_float2(a.x * inv, a.y * inv),
                                           __NV_SATFINITE, __NV_E4M3);
    unsigned p1 = __nv_cvt_float2_to_fp8x2(make_float2(a.z * inv, a.w * inv),
                                           __NV_SATFINITE, __NV_E4M3);
    unsigned p2 = __nv_cvt_float2_to_fp8x2(make_float2(b.x * inv, b.y * inv),
                                           __NV_SATFINITE, __NV_E4M3);
    unsigned p3 = __nv_cvt_float2_to_fp8x2(make_float2(b.z * inv, b.w * inv),
                                           __NV_SATFINITE, __NV_E4M3);
    uint2 pk;
    pk.x = (p0 & 0xffffu) | (p1 << 16);
    pk.y = (p2 & 0xffffu) | (p3 << 16);
    reinterpret_cast<uint2*>(g_nrm)[(size_t)row * (DD / 8) + lane] = pk;
}

// ------------------------------------------------- kernel 2: fused FP8 GEMM (f16 acc), 3 CTA/SM
__global__ __launch_bounds__(256, 3)
void w2ml_main_kernel(const int* __restrict__ labels) {
    extern __shared__ __align__(1024) char smem[];
    const unsigned sbase = (unsigned)__cvta_generic_to_shared(smem);
    const int t = threadIdx.x;

    // decode linear tile id -> (bi, bj), bi <= bj
    int id = blockIdx.x;
    int bi = (int)((2.0f * NT + 1.0f -
                    sqrtf((2.0f * NT + 1.0f) * (2.0f * NT + 1.0f) - 8.0f * (float)id)) * 0.5f);
    while ((bi + 1) * (2 * NT - bi) / 2 <= id) ++bi;
    while (bi * (2 * NT - bi + 1) / 2 > id) --bi;
    const int bj = bi + (id - bi * (2 * NT - bi + 1) / 2);
    const bool diag = (bi == bj);
    const int i0 = bi * BM;
    const int j0 = bj * BN;

    int* sLab = reinterpret_cast<int*>(smem + OFF_LAB);
    float* rowAcc = reinterpret_cast<float*>(smem + OFF_RACC);   // [128] denom
    float* colAcc = reinterpret_cast<float*>(smem + OFF_CACC);   // [128] denom

    if (t < 128) sLab[t] = labels[i0 + t];
    else         sLab[t] = labels[j0 + t - 128];
    if (t < 128) { rowAcc[t] = 0.0f; colAcc[t] = 0.0f; }

    const int lane = t & 31;
    const int warpId = t >> 5;
    const int wm = warpId >> 2;
    const int wn = warpId & 3;

    const uint8_t* gA = g_nrm + (size_t)i0 * DD;
    const uint8_t* gB = g_nrm + (size_t)j0 * DD;

    load_chunk(gA, gB, sbase + OFF_A0, sbase + OFF_B0, 0, t);
    load_chunk(gA, gB, sbase + OFF_A1, sbase + OFF_B1, 1, t);

    const unsigned aRow = (unsigned)((wm * 64 + (lane & 15)) * ROW_B + (lane >> 4) * 16);
    const unsigned bRow = (unsigned)((wn * 32 + (lane & 7) + ((lane >> 4) << 3)) * ROW_B
                                     + ((lane >> 3) & 1) * 16);

    uint32_t acc[4][4][2];
#pragma unroll
    for (int mi = 0; mi < 4; ++mi)
#pragma unroll
        for (int ni = 0; ni < 4; ++ni) { acc[mi][ni][0] = 0u; acc[mi][ni][1] = 0u; }

    asm volatile("cp.async.wait_group 1;" ::: "memory");
    __syncthreads();

#pragma unroll
    for (int kb = 0; kb < 2; ++kb) {
        if (kb == 1) {
            asm volatile("cp.async.wait_group 0;" ::: "memory");
            __syncthreads();
        }
        const unsigned aBase = sbase + (kb ? OFF_A1 : OFF_A0) + aRow;
        const unsigned bBase = sbase + (kb ? OFF_B1 : OFF_B0) + bRow;
#pragma unroll
        for (int ks = 0; ks < 4; ++ks) {
            unsigned off = ks * 32;
            uint32_t bf[4][2];
#pragma unroll
            for (int np = 0; np < 2; ++np) {
                uint32_t r0, r1, r2, r3;
                ldsm4(r0, r1, r2, r3, bBase + np * (16 * ROW_B) + off);
                bf[np * 2][0] = r0;     bf[np * 2][1] = r1;
                bf[np * 2 + 1][0] = r2; bf[np * 2 + 1][1] = r3;
            }
#pragma unroll
            for (int mi = 0; mi < 4; ++mi) {
                uint32_t a[4];
                ldsm4(a[0], a[1], a[2], a[3], aBase + mi * (16 * ROW_B) + off);
#pragma unroll
                for (int ni = 0; ni < 4; ++ni) mma16832h(acc[mi][ni], a, bf[ni]);
            }
        }
    }

    // ---- epilogue: branchless denom accumulation + rare-event branch ----
    const int qrow = lane >> 2;
    const int qc = (lane & 3) << 1;

    int rl0[4], lbr[4][2];
#pragma unroll
    for (int mi = 0; mi < 4; ++mi) {
        rl0[mi] = wm * 64 + mi * 16 + qrow;
        lbr[mi][0] = sLab[rl0[mi]];
        lbr[mi][1] = sLab[rl0[mi] + 8];
    }

    float vrD[4][2];
#pragma unroll
    for (int mi = 0; mi < 4; ++mi) { vrD[mi][0] = 0.0f; vrD[mi][1] = 0.0f; }

#pragma unroll
    for (int ni = 0; ni < 4; ++ni) {
        const int c0 = wn * 32 + ni * 8 + qc;
        const int lj0 = sLab[128 + c0];
        const int lj1 = sLab[128 + c0 + 1];
        float vcD[2] = {0.0f, 0.0f};
#pragma unroll
        for (int mi = 0; mi < 4; ++mi) {
            float2 f01 = __half22float2(*reinterpret_cast<__half2*>(&acc[mi][ni][0]));
            float2 f23 = __half22float2(*reinterpret_cast<__half2*>(&acc[mi][ni][1]));
            float sv[4] = {f01.x, f01.y, f23.x, f23.y};
#pragma unroll
            for (int e = 0; e < 4; ++e) {
                const int h = e >> 1;
                const int o = e & 1;
                const float s = sv[e];
                const float l2 = fmaf(s, C2, -C2);
                const float ex = ex2f(l2);
                vrD[mi][h] += ex;
                vcD[o] += ex;
                const int lj = o ? lj1 : lj0;
                const bool eq = (lbr[mi][h] == lj);
                if (eq || (s > 0.3f)) {                    // rare
                    const int r = rl0[mi] + h * 8;
                    const int c = c0 + o;
                    if (eq) {
                        if (diag && (r == c)) {            // self: remove from denom
                            vrD[mi][h] -= ex;
                            vcD[o] -= ex;
                        } else {                           // true positive
                            const float l = l2 * LN2;
                            const float wp = (s < 0.5f) ? (1.5f - s) : 1.0f;
                            const float s1 = wp * l;
                            atomicAdd(&g_rowstats[NB + i0 + r], s1);
                            atomicAdd(&g_rowstats[2 * NB + i0 + r], wp);
                            atomicAdd(&g_rowstats[3 * NB + i0 + r], ex);
                            if (!diag) {
                                atomicAdd(&g_rowstats[NB + j0 + c], s1);
                                atomicAdd(&g_rowstats[2 * NB + j0 + c], wp);
                                atomicAdd(&g_rowstats[3 * NB + j0 + c], ex);
                            }
                        }
                    } else {                               // hard negative
                        const float add = (s - 0.3f) * ex;
                        atomicAdd(&g_rowstats[4 * NB + i0 + r], add);
                        if (!diag) atomicAdd(&g_rowstats[4 * NB + j0 + c], add);
                    }
                }
            }
        }
        if (!diag) {
#pragma unroll
            for (int o = 0; o < 2; ++o) {
                vcD[o] += __shfl_xor_sync(0xffffffffu, vcD[o], 4);
                vcD[o] += __shfl_xor_sync(0xffffffffu, vcD[o], 8);
                vcD[o] += __shfl_xor_sync(0xffffffffu, vcD[o], 16);
            }
            if (lane < 4) {
                atomicAdd(&colAcc[c0], vcD[0]);
                atomicAdd(&colAcc[c0 + 1], vcD[1]);
            }
        }
    }

#pragma unroll
    for (int mi = 0; mi < 4; ++mi) {
#pragma unroll
        for (int h = 0; h < 2; ++h) {
            vrD[mi][h] += __shfl_xor_sync(0xffffffffu, vrD[mi][h], 1);
            vrD[mi][h] += __shfl_xor_sync(0xffffffffu, vrD[mi][h], 2);
            if ((lane & 3) == 0)
                atomicAdd(&rowAcc[rl0[mi] + h * 8], vrD[mi][h]);
        }
    }
    __syncthreads();

    if (t < 128) {
        atomicAdd(&g_rowstats[i0 + t], rowAcc[t]);
    } else if (!diag) {
        atomicAdd(&g_rowstats[j0 + (t - 128)], colAcc[t - 128]);
    }
}

// ------------------------------------------------- kernel 3: finalize to scalar
__global__ void finalize_kernel(const int* __restrict__ labels, float* __restrict__ out) {
    __shared__ int hist[1024];
    __shared__ float sp[256], sn[256];
    int t = threadIdx.x;
    for (int k = t; k < 1024; k += 256) hist[k] = 0;
    __syncthreads();
    for (int r = t; r < NB; r += 256) atomicAdd(&hist[labels[r]], 1);
    __syncthreads();

    float ps = 0.0f, ns = 0.0f;
    for (int r = t; r < NB; r += 256) {
        float denom = g_rowstats[r];
        float S1 = g_rowstats[NB + r];
        float W1 = g_rowstats[2 * NB + r];
        float Pex = g_rowstats[3 * NB + r];
        float Th = g_rowstats[4 * NB + r];
        float S2 = (denom - Pex) + NEG_SLOPE * Th;   // sum over negatives of w*e
        int pc_actual = hist[labels[r]] - 1;
        float pc = fmaxf((float)pc_actual, 1.0f);
        float nc = fmaxf((float)(NB - 1 - pc_actual), 1.0f);
        float logd = __logf(denom);
        ps -= (S1 - W1 * logd) / pc;
        ns += (S2 / denom) / nc;
    }
    sp[t] = ps; sn[t] = ns;
    __syncthreads();
#pragma unroll
    for (int s = 128; s > 0; s >>= 1) {
        if (t < s) { sp[t] += sp[t + s]; sn[t] += sn[t + s]; }
        __syncthreads();
    }
    if (t == 0) out[0] = sp[0] * (1.0f / NB) + NEG_W * (sn[0] * (1.0f / NB));
}

// ------------------------------------------------- launch
extern "C" void kernel_launch(void* const* d_in, const int* in_sizes, int n_in,
                              void* d_out, int out_size) {
    const float* feat;
    const int* labels;
    if (in_sizes[0] == NB * DD) {
        feat = (const float*)d_in[0];
        labels = (const int*)d_in[1];
    } else {
        feat = (const float*)d_in[1];
        labels = (const int*)d_in[0];
    }

    cudaFuncSetAttribute(w2ml_main_kernel,
                         cudaFuncAttributeMaxDynamicSharedMemorySize, SMEM_BYTES);

    norm_zero_kernel<<<NB / 8, 256>>>(feat);

    w2ml_main_kernel<<<NTILES, 256, SMEM_BYTES>>>(labels);

    finalize_kernel<<<1, 256>>>(labels, (float*)d_out);
}